// round 14
// baseline (speedup 1.0000x reference)
#include <cuda_runtime.h>
#include <cuda_bf16.h>
#include <float.h>

// Scratch (allocation-free rule: __device__ globals; g_key zero at load and
// re-zeroed by the epilogue CTA for graph-replay determinism).
__device__ unsigned long long g_key[4096];   // per-row packed (ordered_val, ~idx)
__device__ int g_argmax[4096];
__device__ unsigned int g_done = 0;

#define NS       6            // pipeline stages (R11 optimum)
#define TILE_F4  1152         // float4 per tile -> 18432 bytes (R11 optimum)
#define TILE_B   (TILE_F4 * 16)
#define THREADS  256
#define NCONS    224          // warps 0-6 consume TMA tiles; warp 7 = LDG stream

__device__ __forceinline__ unsigned int float_ou(float x) {
    unsigned int u = __float_as_uint(x);
    return (u & 0x80000000u) ? ~u : (u | 0x80000000u);
}
__device__ __forceinline__ float ou_float(unsigned int ou) {
    unsigned int u = (ou & 0x80000000u) ? (ou ^ 0x80000000u) : ~ou;
    return __uint_as_float(u);
}
__device__ __forceinline__ unsigned int smem_u32(const void* p) {
    return (unsigned int)__cvta_generic_to_shared(p);
}
__device__ __forceinline__ void mbar_init(unsigned int mbar, unsigned int count) {
    asm volatile("mbarrier.init.shared.b64 [%0], %1;" :: "r"(mbar), "r"(count) : "memory");
}
__device__ __forceinline__ void mbar_expect_tx(unsigned int mbar, unsigned int bytes) {
    asm volatile("mbarrier.arrive.expect_tx.shared.b64 _, [%0], %1;"
                 :: "r"(mbar), "r"(bytes) : "memory");
}
__device__ __forceinline__ void mbar_arrive(unsigned int mbar) {
    asm volatile("mbarrier.arrive.shared.b64 _, [%0];" :: "r"(mbar) : "memory");
}
__device__ __forceinline__ void mbar_wait(unsigned int mbar, unsigned int parity) {
    asm volatile(
        "{\n\t.reg .pred P;\n\t"
        "WAIT_%=:\n\t"
        "mbarrier.try_wait.parity.acquire.cta.shared::cta.b64 P, [%0], %1, 0x989680;\n\t"
        "@P bra.uni DONE_%=;\n\t"
        "bra.uni WAIT_%=;\n\t"
        "DONE_%=:\n\t}"
        :: "r"(mbar), "r"(parity) : "memory");
}
__device__ __forceinline__ void mbar_wait_relaxed(unsigned int mbar, unsigned int parity) {
    asm volatile(
        "{\n\t.reg .pred P;\n\t"
        "WAIT_%=:\n\t"
        "mbarrier.try_wait.parity.relaxed.cta.shared::cta.b64 P, [%0], %1, 0x989680;\n\t"
        "@P bra.uni DONE_%=;\n\t"
        "bra.uni WAIT_%=;\n\t"
        "DONE_%=:\n\t}"
        :: "r"(mbar), "r"(parity) : "memory");
}
__device__ __forceinline__ void bulk_copy_g2s(unsigned int dst_smem, const void* src,
                                              unsigned int bytes, unsigned int mbar) {
    asm volatile(
        "cp.async.bulk.shared::cluster.global.mbarrier::complete_tx::bytes "
        "[%0], [%1], %2, [%3];"
        :: "r"(dst_smem), "l"(src), "r"(bytes), "r"(mbar) : "memory");
}

// Warp-level flush of (best,bidx) into g_key[row]; (value desc, index asc).
__device__ __forceinline__ void warp_flush(float best, int bidx, int row) {
    #pragma unroll
    for (int off = 16; off > 0; off >>= 1) {
        float ov = __shfl_down_sync(0xFFFFFFFFu, best, off);
        int   oi = __shfl_down_sync(0xFFFFFFFFu, bidx, off);
        if (ov > best || (ov == best && oi < bidx)) { best = ov; bidx = oi; }
    }
    if ((threadIdx.x & 31) == 0 && bidx != 0x7FFFFFFF) {
        unsigned long long key =
            ((unsigned long long)float_ou(best) << 32) |
            (unsigned long long)(unsigned int)(~bidx);
        atomicMax(&g_key[row], key);
    }
}

// ---------------------------------------------------------------------------
// Dual-path streaming kernel (R11 base). Each CTA owns a static contiguous
// tile range. Warps 0-6 consume a continuous NS-deep TMA pipeline over the
// first ~7/8 of the range (producer inline at tid 0); warp 7 streams the last
// ~1/8 directly from gmem via __ldcs (independent LSU request path). All
// results merge into g_key[row] via packed atomicMax. Last CTA: accept logic.
// ---------------------------------------------------------------------------
__global__ __launch_bounds__(THREADS, 2)
void rejection_sampler_kernel(const float* __restrict__ logits,
                              const unsigned int* __restrict__ spec_words,
                              float* __restrict__ out,
                              int vocab, int rows, int B, int k) {
    extern __shared__ float4 smem[];
    float4* tiles = smem;
    unsigned long long* bar64 =
        reinterpret_cast<unsigned long long*>(smem + NS * TILE_F4);
    const unsigned int bar_base = smem_u32(bar64);
    #define FULL_BAR(s)  (bar_base + 8u * (unsigned)(s))
    #define EMPTY_BAR(s) (bar_base + 8u * (unsigned)(NS + (s)))

    const int tid = threadIdx.x;
    const int wid = tid >> 5;
    const int lid = tid & 31;
    const int nv4 = vocab >> 2;
    const int tpr = nv4 / TILE_F4;             // full tiles per row
    const int rem_f4 = nv4 - tpr * TILE_F4;    // last partial tile (float4)
    const int tpr_all = tpr + (rem_f4 ? 1 : 0);
    const long long total_tiles = (long long)rows * tpr_all;
    const long long per_cta = (total_tiles + gridDim.x - 1) / gridDim.x;
    long long t0 = (long long)blockIdx.x * per_cta;
    long long t1 = t0 + per_cta; if (t1 > total_tiles) t1 = total_tiles;
    const long long nall = (t1 > t0) ? (t1 - t0) : 0;
    const long long q = nall / 8;              // LDG warp's share (tail of range)
    const long long ntiles = nall - q;         // TMA pipeline share
    const long long ldg0 = t0 + ntiles;        // LDG range [ldg0, t1)

    __shared__ float svals[8];
    __shared__ int   sidx[8];
    __shared__ bool  s_last;

    if (tid == 0) {
        #pragma unroll
        for (int s = 0; s < NS; s++) {
            mbar_init(FULL_BAR(s), 1);
            mbar_init(EMPTY_BAR(s), NCONS);
        }
        asm volatile("fence.proxy.async.shared::cta;" ::: "memory");
    }
    __syncthreads();

    if (wid == 7) {
        // ================= LDG STREAM (warp 7, independent path) ===========
        float best = -FLT_MAX;
        int bidx = 0x7FFFFFFF;
        int cur_row = -1;
        for (long long gt = ldg0; gt < t1; gt++) {
            const int row = (int)(gt / tpr_all);
            const int ti  = (int)(gt % tpr_all);
            if (row != cur_row) {
                if (cur_row >= 0) { warp_flush(best, bidx, cur_row); }
                best = -FLT_MAX; bidx = 0x7FFFFFFF;
                cur_row = row;
            }
            const int f4base = ti * TILE_F4;
            const int n = (ti < tpr) ? TILE_F4 : rem_f4;
            const float4* __restrict__ p4 =
                reinterpret_cast<const float4*>(logits + (size_t)row * vocab) + f4base;
            int j = lid;
            for (; j + 7 * 32 < n; j += 8 * 32) {
                #pragma unroll
                for (int u = 0; u < 8; u++) {
                    float4 v = __ldcs(&p4[j + u * 32]);
                    int base = (f4base + j + u * 32) << 2;
                    if (v.x > best) { best = v.x; bidx = base; }
                    if (v.y > best) { best = v.y; bidx = base + 1; }
                    if (v.z > best) { best = v.z; bidx = base + 2; }
                    if (v.w > best) { best = v.w; bidx = base + 3; }
                }
            }
            for (; j < n; j += 32) {
                float4 v = __ldcs(&p4[j]);
                int base = (f4base + j) << 2;
                if (v.x > best) { best = v.x; bidx = base; }
                if (v.y > best) { best = v.y; bidx = base + 1; }
                if (v.z > best) { best = v.z; bidx = base + 2; }
                if (v.w > best) { best = v.w; bidx = base + 3; }
            }
        }
        if (cur_row >= 0) { warp_flush(best, bidx, cur_row); }
    } else if (ntiles > 0) {
        // ================= TMA PIPELINE (warps 0-6; producer = tid 0) ======
        const int P = (int)((ntiles < (long long)(NS - 1)) ? ntiles : (NS - 1));

        auto tile_src_bytes = [&](long long gt, const float** src, unsigned int* bytes) {
            int row  = (int)(gt / tpr_all);
            int ti   = (int)(gt % tpr_all);
            int n = (ti < tpr) ? TILE_F4 : rem_f4;
            *src = logits + (size_t)row * vocab + (size_t)ti * TILE_F4 * 4;
            *bytes = (unsigned int)(n * 16);
        };

        if (tid == 0) {
            for (int p = 0; p < P; p++) {
                const float* src; unsigned int bytes;
                tile_src_bytes(t0 + p, &src, &bytes);
                mbar_expect_tx(FULL_BAR(p), bytes);
                bulk_copy_g2s(smem_u32(tiles + (size_t)p * TILE_F4), src, bytes, FULL_BAR(p));
            }
        }

        float best = -FLT_MAX;
        int bidx = 0x7FFFFFFF;
        int cur_row = (int)(t0 / tpr_all);

        for (long long g = 0; g < ntiles; g++) {
            const long long gt = t0 + g;
            const int row = (int)(gt / tpr_all);
            const int ti  = (int)(gt % tpr_all);

            if (row != cur_row) {
                #pragma unroll
                for (int off = 16; off > 0; off >>= 1) {
                    float ov = __shfl_down_sync(0xFFFFFFFFu, best, off);
                    int   oi = __shfl_down_sync(0xFFFFFFFFu, bidx, off);
                    if (ov > best || (ov == best && oi < bidx)) { best = ov; bidx = oi; }
                }
                if (lid == 0 && bidx != 0x7FFFFFFF) {
                    unsigned long long key =
                        ((unsigned long long)float_ou(best) << 32) |
                        (unsigned long long)(unsigned int)(~bidx);
                    atomicMax(&g_key[cur_row], key);
                }
                best = -FLT_MAX; bidx = 0x7FFFFFFF;
                cur_row = row;
            }

            const int s = (int)(g % NS);
            mbar_wait(FULL_BAR(s), (unsigned)((g / NS) & 1));

            const int f4base = ti * TILE_F4;
            const int n = (ti < tpr) ? TILE_F4 : rem_f4;
            const float4* tp = tiles + (size_t)s * TILE_F4;
            for (int j = tid; j < n; j += NCONS) {
                float4 v = tp[j];
                int base = (f4base + j) << 2;
                // Per-thread indices strictly increase within a row, so strict
                // '>' keeps earliest index on ties (jnp.argmax semantics).
                if (v.x > best) { best = v.x; bidx = base; }
                if (v.y > best) { best = v.y; bidx = base + 1; }
                if (v.z > best) { best = v.z; bidx = base + 2; }
                if (v.w > best) { best = v.w; bidx = base + 3; }
            }
            mbar_arrive(EMPTY_BAR(s));

            if (tid == 0 && g + P < ntiles) {
                const long long gg = g + P;
                const int ss = (int)(gg % NS);
                const long long ii = gg / NS;
                if (ii >= 1) mbar_wait_relaxed(EMPTY_BAR(ss), (unsigned)((ii - 1) & 1));
                const float* src; unsigned int bytes;
                tile_src_bytes(t0 + gg, &src, &bytes);
                mbar_expect_tx(FULL_BAR(ss), bytes);
                bulk_copy_g2s(smem_u32(tiles + (size_t)ss * TILE_F4), src, bytes, FULL_BAR(ss));
            }
        }

        // final flush (warp-level; cross-warp merge happens via atomicMax)
        #pragma unroll
        for (int off = 16; off > 0; off >>= 1) {
            float ov = __shfl_down_sync(0xFFFFFFFFu, best, off);
            int   oi = __shfl_down_sync(0xFFFFFFFFu, bidx, off);
            if (ov > best || (ov == best && oi < bidx)) { best = ov; bidx = oi; }
        }
        if (lid == 0 && bidx != 0x7FFFFFFF) {
            unsigned long long key =
                ((unsigned long long)float_ou(best) << 32) |
                (unsigned long long)(unsigned int)(~bidx);
            atomicMax(&g_key[cur_row], key);
        }
    }
    __syncthreads();

    // ---- completion counter ----
    if (tid == 0) {
        __threadfence();
        unsigned int prev = atomicAdd(&g_done, 1u);
        s_last = (prev == gridDim.x - 1u);
    }
    __syncthreads();
    if (!s_last) return;
    __threadfence();   // acquire all CTAs' key updates

    // ---- decode per-row argmax (+ scalar tail if vocab % 4 != 0) ----
    const int remv = vocab & 3;
    for (int r = tid; r < rows; r += THREADS) {
        unsigned long long key = g_key[r];
        int idx = ~(int)(unsigned int)(key & 0xFFFFFFFFull);
        if (remv) {
            float val = ou_float((unsigned int)(key >> 32));
            const float* rowp = logits + (size_t)r * vocab;
            for (int c = nv4 << 2; c < vocab; c++) {
                float v = rowp[c];
                if (v > val) { val = v; idx = c; }
            }
        }
        g_argmax[r] = idx;
    }
    __syncthreads();

    // ---- speculative-accept logic ----
    if (tid < B) {
        const int b = tid;
        // spec dtype detection: tokens < 2^17 -> int words < 0x20000;
        // float32 (>=1.0) patterns >= 0x3F800000; int64 -> odd words zero.
        int big = 0, odd_nonzero = 0;
        #pragma unroll
        for (int w = 0; w < 32; w++) {
            unsigned int x = spec_words[w];
            if (x >= 0x01000000u) big++;
            if ((w & 1) && x != 0u) odd_nonzero++;
        }
        int mode = (big > 0) ? 2 : (odd_nonzero == 0 ? 1 : 0); // 2=f32,1=i64,0=i32

        const int kp1 = k + 1;
        int n_acc = 0;
        bool acc = true;
        for (int j = 0; j < k; j++) {
            long long sv;
            if (mode == 2) {
                float f = reinterpret_cast<const float*>(spec_words)[(size_t)b * k + j];
                sv = (long long)f;
            } else if (mode == 1) {
                sv = reinterpret_cast<const long long*>(spec_words)[(size_t)b * k + j];
            } else {
                sv = (long long)reinterpret_cast<const int*>(spec_words)[(size_t)b * k + j];
            }
            int o = g_argmax[b * kp1 + j];
            if (acc && (long long)o == sv) n_acc++; else acc = false;
        }
        for (int j = 0; j < kp1; j++) {
            out[b * kp1 + j] = (j <= n_acc) ? (float)g_argmax[b * kp1 + j] : -1.0f;
        }
    }
    __syncthreads();
    for (int r = tid; r < rows; r += THREADS) g_key[r] = 0ull;
    if (tid == 0) g_done = 0;
}

extern "C" void kernel_launch(void* const* d_in, const int* in_sizes, int n_in,
                              void* d_out, int out_size) {
    const float* logits = (const float*)d_in[0];
    const unsigned int* spec = (const unsigned int*)d_in[1];

    const int rows  = out_size;          // B*(k+1)
    const int nspec = in_sizes[1];       // B*k
    const int B     = rows - nspec;
    const int k     = nspec / B;
    const int vocab = (int)((long long)in_sizes[0] / rows);

    int sms = 148;
    cudaDeviceGetAttribute(&sms, cudaDevAttrMultiProcessorCount, 0);
    const int grid = sms * 2;            // 2 CTAs/SM: dual TMA+LDG paths each

    const int smem_bytes = NS * TILE_B + 2 * NS * 8 + 16;
    static int configured = 0;
    if (!configured) {
        cudaFuncSetAttribute(rejection_sampler_kernel,
                             cudaFuncAttributeMaxDynamicSharedMemorySize, smem_bytes);
        configured = 1;
    }

    rejection_sampler_kernel<<<grid, THREADS, smem_bytes>>>(
        logits, spec, (float*)d_out, vocab, rows, B, k);
}

// round 15
// speedup vs baseline: 1.1263x; 1.1263x over previous
#include <cuda_runtime.h>
#include <cuda_bf16.h>
#include <float.h>

// Scratch (allocation-free rule: __device__ globals; g_key zero at load and
// re-zeroed by the epilogue CTA for graph-replay determinism).
__device__ unsigned long long g_key[4096];   // per-row packed (ordered_val, ~idx)
__device__ int g_argmax[4096];
__device__ unsigned int g_done = 0;

#define NS       6            // pipeline stages (R11 optimum)
#define TILE_F4  1152         // float4 per tile -> 18432 bytes (R11 optimum)
#define TILE_B   (TILE_F4 * 16)
#define THREADS  256
#define NWARPS   (THREADS / 32)

__device__ __forceinline__ unsigned int float_ou(float x) {
    unsigned int u = __float_as_uint(x);
    return (u & 0x80000000u) ? ~u : (u | 0x80000000u);
}
__device__ __forceinline__ float ou_float(unsigned int ou) {
    unsigned int u = (ou & 0x80000000u) ? (ou ^ 0x80000000u) : ~ou;
    return __uint_as_float(u);
}
__device__ __forceinline__ unsigned int smem_u32(const void* p) {
    return (unsigned int)__cvta_generic_to_shared(p);
}
__device__ __forceinline__ void mbar_init(unsigned int mbar, unsigned int count) {
    asm volatile("mbarrier.init.shared.b64 [%0], %1;" :: "r"(mbar), "r"(count) : "memory");
}
__device__ __forceinline__ void mbar_expect_tx(unsigned int mbar, unsigned int bytes) {
    asm volatile("mbarrier.arrive.expect_tx.shared.b64 _, [%0], %1;"
                 :: "r"(mbar), "r"(bytes) : "memory");
}
__device__ __forceinline__ void mbar_arrive(unsigned int mbar) {
    asm volatile("mbarrier.arrive.shared.b64 _, [%0];" :: "r"(mbar) : "memory");
}
__device__ __forceinline__ void mbar_wait(unsigned int mbar, unsigned int parity) {
    asm volatile(
        "{\n\t.reg .pred P;\n\t"
        "WAIT_%=:\n\t"
        "mbarrier.try_wait.parity.acquire.cta.shared::cta.b64 P, [%0], %1, 0x989680;\n\t"
        "@P bra.uni DONE_%=;\n\t"
        "bra.uni WAIT_%=;\n\t"
        "DONE_%=:\n\t}"
        :: "r"(mbar), "r"(parity) : "memory");
}
__device__ __forceinline__ void mbar_wait_relaxed(unsigned int mbar, unsigned int parity) {
    asm volatile(
        "{\n\t.reg .pred P;\n\t"
        "WAIT_%=:\n\t"
        "mbarrier.try_wait.parity.relaxed.cta.shared::cta.b64 P, [%0], %1, 0x989680;\n\t"
        "@P bra.uni DONE_%=;\n\t"
        "bra.uni WAIT_%=;\n\t"
        "DONE_%=:\n\t}"
        :: "r"(mbar), "r"(parity) : "memory");
}
__device__ __forceinline__ void bulk_copy_g2s(unsigned int dst_smem, const void* src,
                                              unsigned int bytes, unsigned int mbar) {
    asm volatile(
        "cp.async.bulk.shared::cluster.global.mbarrier::complete_tx::bytes "
        "[%0], [%1], %2, [%3];"
        :: "r"(dst_smem), "l"(src), "r"(bytes), "r"(mbar) : "memory");
}

// ---------------------------------------------------------------------------
// R11 architecture (measured optimum: 2 pipelines/SM, NS=6 x 18432B, 256 thr,
// producer inline at tid 0) with one micro-fix: per-warp elected empty-arrives
// (8 smem-atomic ops per tile instead of 256). Each CTA owns a static
// contiguous tile range (tiles never span rows) and streams it through ONE
// uninterrupted NS-deep cp.async.bulk pipeline. Row boundaries flush the
// running argmax into g_key[row] (packed atomicMax encoding value-desc /
// index-asc). Last-finishing CTA decodes keys + runs the accept epilogue.
// ---------------------------------------------------------------------------
__global__ __launch_bounds__(THREADS, 2)
void rejection_sampler_kernel(const float* __restrict__ logits,
                              const unsigned int* __restrict__ spec_words,
                              float* __restrict__ out,
                              int vocab, int rows, int B, int k) {
    extern __shared__ float4 smem[];
    float4* tiles = smem;
    unsigned long long* bar64 =
        reinterpret_cast<unsigned long long*>(smem + NS * TILE_F4);
    const unsigned int bar_base = smem_u32(bar64);
    #define FULL_BAR(s)  (bar_base + 8u * (unsigned)(s))
    #define EMPTY_BAR(s) (bar_base + 8u * (unsigned)(NS + (s)))

    const int tid = threadIdx.x;
    const int wid = tid >> 5;
    const int lid = tid & 31;
    const int nv4 = vocab >> 2;
    const int tpr = nv4 / TILE_F4;             // full tiles per row
    const int rem_f4 = nv4 - tpr * TILE_F4;    // last partial tile (float4)
    const int tpr_all = tpr + (rem_f4 ? 1 : 0);
    const long long total_tiles = (long long)rows * tpr_all;
    const long long per_cta = (total_tiles + gridDim.x - 1) / gridDim.x;
    long long t0 = (long long)blockIdx.x * per_cta;
    long long t1 = t0 + per_cta; if (t1 > total_tiles) t1 = total_tiles;
    const long long ntiles = (t1 > t0) ? (t1 - t0) : 0;

    __shared__ float svals[NWARPS];
    __shared__ int   sidx[NWARPS];
    __shared__ bool  s_last;

    if (tid == 0) {
        #pragma unroll
        for (int s = 0; s < NS; s++) {
            mbar_init(FULL_BAR(s), 1);        // completes via expect_tx bytes
            mbar_init(EMPTY_BAR(s), NWARPS);  // one elected arrive per warp
        }
        asm volatile("fence.proxy.async.shared::cta;" ::: "memory");
    }
    __syncthreads();

    if (ntiles > 0) {
        const int P = (int)((ntiles < (long long)(NS - 1)) ? ntiles : (NS - 1));

        auto tile_src_bytes = [&](long long gt, const float** src, unsigned int* bytes) {
            int row  = (int)(gt / tpr_all);
            int ti   = (int)(gt % tpr_all);
            int n = (ti < tpr) ? TILE_F4 : rem_f4;
            *src = logits + (size_t)row * vocab + (size_t)ti * TILE_F4 * 4;
            *bytes = (unsigned int)(n * 16);
        };

        // ---- prologue: fill pipeline ----
        if (tid == 0) {
            for (int p = 0; p < P; p++) {
                const float* src; unsigned int bytes;
                tile_src_bytes(t0 + p, &src, &bytes);
                mbar_expect_tx(FULL_BAR(p), bytes);
                bulk_copy_g2s(smem_u32(tiles + (size_t)p * TILE_F4), src, bytes, FULL_BAR(p));
            }
        }

        float best = -FLT_MAX;
        int bidx = 0x7FFFFFFF;
        int cur_row = (int)(t0 / tpr_all);

        for (long long g = 0; g < ntiles; g++) {
            const long long gt = t0 + g;
            const int row = (int)(gt / tpr_all);
            const int ti  = (int)(gt % tpr_all);

            // ---- row-boundary flush ----
            if (row != cur_row) {
                #pragma unroll
                for (int off = 16; off > 0; off >>= 1) {
                    float ov = __shfl_down_sync(0xFFFFFFFFu, best, off);
                    int   oi = __shfl_down_sync(0xFFFFFFFFu, bidx, off);
                    if (ov > best || (ov == best && oi < bidx)) { best = ov; bidx = oi; }
                }
                if (lid == 0) { svals[wid] = best; sidx[wid] = bidx; }
                __syncthreads();
                if (wid == 0) {
                    float bv = (lid < NWARPS) ? svals[lid] : -FLT_MAX;
                    int   bi = (lid < NWARPS) ? sidx[lid]  : 0x7FFFFFFF;
                    #pragma unroll
                    for (int off = 4; off > 0; off >>= 1) {
                        float ov = __shfl_down_sync(0xFFFFFFFFu, bv, off);
                        int   oi = __shfl_down_sync(0xFFFFFFFFu, bi, off);
                        if (ov > bv || (ov == bv && oi < bi)) { bv = ov; bi = oi; }
                    }
                    if (lid == 0 && bi != 0x7FFFFFFF) {
                        unsigned long long key =
                            ((unsigned long long)float_ou(bv) << 32) |
                            (unsigned long long)(unsigned int)(~bi);
                        atomicMax(&g_key[cur_row], key);
                    }
                }
                __syncthreads();
                best = -FLT_MAX; bidx = 0x7FFFFFFF;
                cur_row = row;
            }

            // ---- consume tile g ----
            const int s = (int)(g % NS);
            mbar_wait(FULL_BAR(s), (unsigned)((g / NS) & 1));

            const int f4base = ti * TILE_F4;
            const int n = (ti < tpr) ? TILE_F4 : rem_f4;
            const float4* tp = tiles + (size_t)s * TILE_F4;
            for (int j = tid; j < n; j += THREADS) {
                float4 v = tp[j];
                int base = (f4base + j) << 2;
                // Per-thread indices strictly increase within a row, so strict
                // '>' keeps the earliest index on ties (jnp.argmax semantics).
                if (v.x > best) { best = v.x; bidx = base; }
                if (v.y > best) { best = v.y; bidx = base + 1; }
                if (v.z > best) { best = v.z; bidx = base + 2; }
                if (v.w > best) { best = v.w; bidx = base + 3; }
            }
            // Per-warp elected empty-arrive: warp-local ordering is enough
            // because all reads of this stage by this warp precede syncwarp.
            __syncwarp();
            if (lid == 0) mbar_arrive(EMPTY_BAR(s));

            // ---- produce tile g+P (continuous; never drains) ----
            if (tid == 0 && g + P < ntiles) {
                const long long gg = g + P;
                const int ss = (int)(gg % NS);
                const long long ii = gg / NS;
                if (ii >= 1) mbar_wait_relaxed(EMPTY_BAR(ss), (unsigned)((ii - 1) & 1));
                const float* src; unsigned int bytes;
                tile_src_bytes(t0 + gg, &src, &bytes);
                mbar_expect_tx(FULL_BAR(ss), bytes);
                bulk_copy_g2s(smem_u32(tiles + (size_t)ss * TILE_F4), src, bytes, FULL_BAR(ss));
            }
        }

        // ---- final flush ----
        #pragma unroll
        for (int off = 16; off > 0; off >>= 1) {
            float ov = __shfl_down_sync(0xFFFFFFFFu, best, off);
            int   oi = __shfl_down_sync(0xFFFFFFFFu, bidx, off);
            if (ov > best || (ov == best && oi < bidx)) { best = ov; bidx = oi; }
        }
        if (lid == 0) { svals[wid] = best; sidx[wid] = bidx; }
        __syncthreads();
        if (wid == 0) {
            float bv = (lid < NWARPS) ? svals[lid] : -FLT_MAX;
            int   bi = (lid < NWARPS) ? sidx[lid]  : 0x7FFFFFFF;
            #pragma unroll
            for (int off = 4; off > 0; off >>= 1) {
                float ov = __shfl_down_sync(0xFFFFFFFFu, bv, off);
                int   oi = __shfl_down_sync(0xFFFFFFFFu, bi, off);
                if (ov > bv || (ov == bv && oi < bi)) { bv = ov; bi = oi; }
            }
            if (lid == 0 && bi != 0x7FFFFFFF) {
                unsigned long long key =
                    ((unsigned long long)float_ou(bv) << 32) |
                    (unsigned long long)(unsigned int)(~bi);
                atomicMax(&g_key[cur_row], key);
            }
        }
    }
    __syncthreads();

    // ---- completion counter ----
    if (tid == 0) {
        __threadfence();
        unsigned int prev = atomicAdd(&g_done, 1u);
        s_last = (prev == gridDim.x - 1u);
    }
    __syncthreads();
    if (!s_last) return;
    __threadfence();   // acquire all CTAs' key updates

    // ---- decode per-row argmax (+ scalar tail if vocab % 4 != 0) ----
    const int remv = vocab & 3;
    for (int r = tid; r < rows; r += THREADS) {
        unsigned long long key = g_key[r];
        int idx = ~(int)(unsigned int)(key & 0xFFFFFFFFull);
        if (remv) {
            float val = ou_float((unsigned int)(key >> 32));
            const float* rowp = logits + (size_t)r * vocab;
            for (int c = nv4 << 2; c < vocab; c++) {
                float v = rowp[c];
                if (v > val) { val = v; idx = c; }
            }
        }
        g_argmax[r] = idx;
    }
    __syncthreads();

    // ---- speculative-accept logic ----
    if (tid < B) {
        const int b = tid;
        // spec dtype detection: tokens < 2^17 -> int words < 0x20000;
        // float32 (>=1.0) patterns >= 0x3F800000; int64 -> odd words zero.
        int big = 0, odd_nonzero = 0;
        #pragma unroll
        for (int w = 0; w < 32; w++) {
            unsigned int x = spec_words[w];
            if (x >= 0x01000000u) big++;
            if ((w & 1) && x != 0u) odd_nonzero++;
        }
        int mode = (big > 0) ? 2 : (odd_nonzero == 0 ? 1 : 0); // 2=f32,1=i64,0=i32

        const int kp1 = k + 1;
        int n_acc = 0;
        bool acc = true;
        for (int j = 0; j < k; j++) {
            long long sv;
            if (mode == 2) {
                float f = reinterpret_cast<const float*>(spec_words)[(size_t)b * k + j];
                sv = (long long)f;
            } else if (mode == 1) {
                sv = reinterpret_cast<const long long*>(spec_words)[(size_t)b * k + j];
            } else {
                sv = (long long)reinterpret_cast<const int*>(spec_words)[(size_t)b * k + j];
            }
            int o = g_argmax[b * kp1 + j];
            if (acc && (long long)o == sv) n_acc++; else acc = false;
        }
        for (int j = 0; j < kp1; j++) {
            out[b * kp1 + j] = (j <= n_acc) ? (float)g_argmax[b * kp1 + j] : -1.0f;
        }
    }
    __syncthreads();
    for (int r = tid; r < rows; r += THREADS) g_key[r] = 0ull;
    if (tid == 0) g_done = 0;
}

extern "C" void kernel_launch(void* const* d_in, const int* in_sizes, int n_in,
                              void* d_out, int out_size) {
    const float* logits = (const float*)d_in[0];
    const unsigned int* spec = (const unsigned int*)d_in[1];

    const int rows  = out_size;          // B*(k+1)
    const int nspec = in_sizes[1];       // B*k
    const int B     = rows - nspec;
    const int k     = nspec / B;
    const int vocab = (int)((long long)in_sizes[0] / rows);

    int sms = 148;
    cudaDeviceGetAttribute(&sms, cudaDevAttrMultiProcessorCount, 0);
    const int grid = sms * 2;            // 2 pipelines/SM, ~110.7KB smem each

    const int smem_bytes = NS * TILE_B + 2 * NS * 8 + 16;
    static int configured = 0;
    if (!configured) {
        cudaFuncSetAttribute(rejection_sampler_kernel,
                             cudaFuncAttributeMaxDynamicSharedMemorySize, smem_bytes);
        configured = 1;
    }

    rejection_sampler_kernel<<<grid, THREADS, smem_bytes>>>(
        logits, spec, (float*)d_out, vocab, rows, B, k);
}

// round 16
// speedup vs baseline: 1.1477x; 1.0190x over previous
#include <cuda_runtime.h>
#include <cuda_bf16.h>
#include <float.h>

// Scratch (allocation-free rule: __device__ globals; g_key zero at load and
// re-zeroed by the epilogue CTA for graph-replay determinism).
__device__ unsigned long long g_key[4096];   // per-row packed (ordered_val, ~idx)
__device__ int g_argmax[4096];
__device__ unsigned int g_done = 0;

#define NS       6            // pipeline stages (R11/R15 optimum)
#define TILE_F4  1152         // float4 per tile -> 18432 bytes (optimum)
#define TILE_B   (TILE_F4 * 16)
#define THREADS  256
#define NWARPS   (THREADS / 32)

__device__ __forceinline__ unsigned int float_ou(float x) {
    unsigned int u = __float_as_uint(x);
    return (u & 0x80000000u) ? ~u : (u | 0x80000000u);
}
__device__ __forceinline__ float ou_float(unsigned int ou) {
    unsigned int u = (ou & 0x80000000u) ? (ou ^ 0x80000000u) : ~ou;
    return __uint_as_float(u);
}
__device__ __forceinline__ unsigned int smem_u32(const void* p) {
    return (unsigned int)__cvta_generic_to_shared(p);
}
__device__ __forceinline__ void mbar_init(unsigned int mbar, unsigned int count) {
    asm volatile("mbarrier.init.shared.b64 [%0], %1;" :: "r"(mbar), "r"(count) : "memory");
}
__device__ __forceinline__ void mbar_expect_tx(unsigned int mbar, unsigned int bytes) {
    asm volatile("mbarrier.arrive.expect_tx.shared.b64 _, [%0], %1;"
                 :: "r"(mbar), "r"(bytes) : "memory");
}
__device__ __forceinline__ void mbar_arrive(unsigned int mbar) {
    asm volatile("mbarrier.arrive.shared.b64 _, [%0];" :: "r"(mbar) : "memory");
}
__device__ __forceinline__ void mbar_wait(unsigned int mbar, unsigned int parity) {
    asm volatile(
        "{\n\t.reg .pred P;\n\t"
        "WAIT_%=:\n\t"
        "mbarrier.try_wait.parity.acquire.cta.shared::cta.b64 P, [%0], %1, 0x989680;\n\t"
        "@P bra.uni DONE_%=;\n\t"
        "bra.uni WAIT_%=;\n\t"
        "DONE_%=:\n\t}"
        :: "r"(mbar), "r"(parity) : "memory");
}
__device__ __forceinline__ void mbar_wait_relaxed(unsigned int mbar, unsigned int parity) {
    asm volatile(
        "{\n\t.reg .pred P;\n\t"
        "WAIT_%=:\n\t"
        "mbarrier.try_wait.parity.relaxed.cta.shared::cta.b64 P, [%0], %1, 0x989680;\n\t"
        "@P bra.uni DONE_%=;\n\t"
        "bra.uni WAIT_%=;\n\t"
        "DONE_%=:\n\t}"
        :: "r"(mbar), "r"(parity) : "memory");
}
__device__ __forceinline__ void bulk_copy_g2s(unsigned int dst_smem, const void* src,
                                              unsigned int bytes, unsigned int mbar) {
    asm volatile(
        "cp.async.bulk.shared::cluster.global.mbarrier::complete_tx::bytes "
        "[%0], [%1], %2, [%3];"
        :: "r"(dst_smem), "l"(src), "r"(bytes), "r"(mbar) : "memory");
}

// Warp-level flush of (best,bidx) into g_key[row]; (value desc, index asc).
__device__ __forceinline__ void warp_flush(float best, int bidx, int row) {
    #pragma unroll
    for (int off = 16; off > 0; off >>= 1) {
        float ov = __shfl_down_sync(0xFFFFFFFFu, best, off);
        int   oi = __shfl_down_sync(0xFFFFFFFFu, bidx, off);
        if (ov > best || (ov == best && oi < bidx)) { best = ov; bidx = oi; }
    }
    if ((threadIdx.x & 31) == 0 && bidx != 0x7FFFFFFF) {
        unsigned long long key =
            ((unsigned long long)float_ou(best) << 32) |
            (unsigned long long)(unsigned int)(~bidx);
        atomicMax(&g_key[row], key);
    }
}

// ---------------------------------------------------------------------------
// R15 architecture (measured optimum) with two micro-fixes:
//  (1) dual independent accumulator chains per thread (halves the serial
//      compare-select dependency in tile drain),
//  (2) warp-level row flushes straight to atomicMax (no block reduce, no
//      __syncthreads on row boundaries).
// Each CTA owns a static contiguous tile range (tiles never span rows) and
// streams it through ONE uninterrupted NS-deep cp.async.bulk pipeline
// (producer inline at tid 0, per-warp elected empty-arrives). Last-finishing
// CTA decodes keys + runs the accept epilogue.
// ---------------------------------------------------------------------------
__global__ __launch_bounds__(THREADS, 2)
void rejection_sampler_kernel(const float* __restrict__ logits,
                              const unsigned int* __restrict__ spec_words,
                              float* __restrict__ out,
                              int vocab, int rows, int B, int k) {
    extern __shared__ float4 smem[];
    float4* tiles = smem;
    unsigned long long* bar64 =
        reinterpret_cast<unsigned long long*>(smem + NS * TILE_F4);
    const unsigned int bar_base = smem_u32(bar64);
    #define FULL_BAR(s)  (bar_base + 8u * (unsigned)(s))
    #define EMPTY_BAR(s) (bar_base + 8u * (unsigned)(NS + (s)))

    const int tid = threadIdx.x;
    const int lid = tid & 31;
    const int nv4 = vocab >> 2;
    const int tpr = nv4 / TILE_F4;             // full tiles per row
    const int rem_f4 = nv4 - tpr * TILE_F4;    // last partial tile (float4)
    const int tpr_all = tpr + (rem_f4 ? 1 : 0);
    const long long total_tiles = (long long)rows * tpr_all;
    const long long per_cta = (total_tiles + gridDim.x - 1) / gridDim.x;
    long long t0 = (long long)blockIdx.x * per_cta;
    long long t1 = t0 + per_cta; if (t1 > total_tiles) t1 = total_tiles;
    const long long ntiles = (t1 > t0) ? (t1 - t0) : 0;

    __shared__ bool s_last;

    if (tid == 0) {
        #pragma unroll
        for (int s = 0; s < NS; s++) {
            mbar_init(FULL_BAR(s), 1);        // completes via expect_tx bytes
            mbar_init(EMPTY_BAR(s), NWARPS);  // one elected arrive per warp
        }
        asm volatile("fence.proxy.async.shared::cta;" ::: "memory");
    }
    __syncthreads();

    if (ntiles > 0) {
        const int P = (int)((ntiles < (long long)(NS - 1)) ? ntiles : (NS - 1));

        auto tile_src_bytes = [&](long long gt, const float** src, unsigned int* bytes) {
            int row  = (int)(gt / tpr_all);
            int ti   = (int)(gt % tpr_all);
            int n = (ti < tpr) ? TILE_F4 : rem_f4;
            *src = logits + (size_t)row * vocab + (size_t)ti * TILE_F4 * 4;
            *bytes = (unsigned int)(n * 16);
        };

        // ---- prologue: fill pipeline ----
        if (tid == 0) {
            for (int p = 0; p < P; p++) {
                const float* src; unsigned int bytes;
                tile_src_bytes(t0 + p, &src, &bytes);
                mbar_expect_tx(FULL_BAR(p), bytes);
                bulk_copy_g2s(smem_u32(tiles + (size_t)p * TILE_F4), src, bytes, FULL_BAR(p));
            }
        }

        // dual accumulator chains (chain0: .x/.y, chain1: .z/.w)
        float best0 = -FLT_MAX, best1 = -FLT_MAX;
        int   bidx0 = 0x7FFFFFFF, bidx1 = 0x7FFFFFFF;
        int cur_row = (int)(t0 / tpr_all);

        for (long long g = 0; g < ntiles; g++) {
            const long long gt = t0 + g;
            const int row = (int)(gt / tpr_all);
            const int ti  = (int)(gt % tpr_all);

            // ---- row-boundary flush (warp-level, no block sync) ----
            if (row != cur_row) {
                // merge chains: value desc, index asc (exact argmax order)
                float mb = best0; int mi = bidx0;
                if (best1 > mb || (best1 == mb && bidx1 < mi)) { mb = best1; mi = bidx1; }
                warp_flush(mb, mi, cur_row);
                best0 = best1 = -FLT_MAX;
                bidx0 = bidx1 = 0x7FFFFFFF;
                cur_row = row;
            }

            // ---- consume tile g ----
            const int s = (int)(g % NS);
            mbar_wait(FULL_BAR(s), (unsigned)((g / NS) & 1));

            const int f4base = ti * TILE_F4;
            const int n = (ti < tpr) ? TILE_F4 : rem_f4;
            const float4* tp = tiles + (size_t)s * TILE_F4;
            for (int j = tid; j < n; j += THREADS) {
                float4 v = tp[j];
                int base = (f4base + j) << 2;
                // Two independent chains; per-thread indices strictly
                // increase within each chain -> strict '>' keeps earliest
                // index per chain (merged with index tie-break at flush).
                if (v.x > best0) { best0 = v.x; bidx0 = base; }
                if (v.y > best0) { best0 = v.y; bidx0 = base + 1; }
                if (v.z > best1) { best1 = v.z; bidx1 = base + 2; }
                if (v.w > best1) { best1 = v.w; bidx1 = base + 3; }
            }
            // Per-warp elected empty-arrive.
            __syncwarp();
            if (lid == 0) mbar_arrive(EMPTY_BAR(s));

            // ---- produce tile g+P (continuous; never drains) ----
            if (tid == 0 && g + P < ntiles) {
                const long long gg = g + P;
                const int ss = (int)(gg % NS);
                const long long ii = gg / NS;
                if (ii >= 1) mbar_wait_relaxed(EMPTY_BAR(ss), (unsigned)((ii - 1) & 1));
                const float* src; unsigned int bytes;
                tile_src_bytes(t0 + gg, &src, &bytes);
                mbar_expect_tx(FULL_BAR(ss), bytes);
                bulk_copy_g2s(smem_u32(tiles + (size_t)ss * TILE_F4), src, bytes, FULL_BAR(ss));
            }
        }

        // ---- final flush ----
        {
            float mb = best0; int mi = bidx0;
            if (best1 > mb || (best1 == mb && bidx1 < mi)) { mb = best1; mi = bidx1; }
            warp_flush(mb, mi, cur_row);
        }
    }
    __syncthreads();

    // ---- completion counter ----
    if (tid == 0) {
        __threadfence();
        unsigned int prev = atomicAdd(&g_done, 1u);
        s_last = (prev == gridDim.x - 1u);
    }
    __syncthreads();
    if (!s_last) return;
    __threadfence();   // acquire all CTAs' key updates

    // ---- decode per-row argmax (+ scalar tail if vocab % 4 != 0) ----
    const int remv = vocab & 3;
    for (int r = tid; r < rows; r += THREADS) {
        unsigned long long key = g_key[r];
        int idx = ~(int)(unsigned int)(key & 0xFFFFFFFFull);
        if (remv) {
            float val = ou_float((unsigned int)(key >> 32));
            const float* rowp = logits + (size_t)r * vocab;
            for (int c = nv4 << 2; c < vocab; c++) {
                float v = rowp[c];
                if (v > val) { val = v; idx = c; }
            }
        }
        g_argmax[r] = idx;
    }
    __syncthreads();

    // ---- speculative-accept logic ----
    if (tid < B) {
        const int b = tid;
        // spec dtype detection: tokens < 2^17 -> int words < 0x20000;
        // float32 (>=1.0) patterns >= 0x3F800000; int64 -> odd words zero.
        int big = 0, odd_nonzero = 0;
        #pragma unroll
        for (int w = 0; w < 32; w++) {
            unsigned int x = spec_words[w];
            if (x >= 0x01000000u) big++;
            if ((w & 1) && x != 0u) odd_nonzero++;
        }
        int mode = (big > 0) ? 2 : (odd_nonzero == 0 ? 1 : 0); // 2=f32,1=i64,0=i32

        const int kp1 = k + 1;
        int n_acc = 0;
        bool acc = true;
        for (int j = 0; j < k; j++) {
            long long sv;
            if (mode == 2) {
                float f = reinterpret_cast<const float*>(spec_words)[(size_t)b * k + j];
                sv = (long long)f;
            } else if (mode == 1) {
                sv = reinterpret_cast<const long long*>(spec_words)[(size_t)b * k + j];
            } else {
                sv = (long long)reinterpret_cast<const int*>(spec_words)[(size_t)b * k + j];
            }
            int o = g_argmax[b * kp1 + j];
            if (acc && (long long)o == sv) n_acc++; else acc = false;
        }
        for (int j = 0; j < kp1; j++) {
            out[b * kp1 + j] = (j <= n_acc) ? (float)g_argmax[b * kp1 + j] : -1.0f;
        }
    }
    __syncthreads();
    for (int r = tid; r < rows; r += THREADS) g_key[r] = 0ull;
    if (tid == 0) g_done = 0;
}

extern "C" void kernel_launch(void* const* d_in, const int* in_sizes, int n_in,
                              void* d_out, int out_size) {
    const float* logits = (const float*)d_in[0];
    const unsigned int* spec = (const unsigned int*)d_in[1];

    const int rows  = out_size;          // B*(k+1)
    const int nspec = in_sizes[1];       // B*k
    const int B     = rows - nspec;
    const int k     = nspec / B;
    const int vocab = (int)((long long)in_sizes[0] / rows);

    int sms = 148;
    cudaDeviceGetAttribute(&sms, cudaDevAttrMultiProcessorCount, 0);
    const int grid = sms * 2;            // 2 pipelines/SM, ~110.7KB smem each

    const int smem_bytes = NS * TILE_B + 2 * NS * 8 + 16;
    static int configured = 0;
    if (!configured) {
        cudaFuncSetAttribute(rejection_sampler_kernel,
                             cudaFuncAttributeMaxDynamicSharedMemorySize, smem_bytes);
        configured = 1;
    }

    rejection_sampler_kernel<<<grid, THREADS, smem_bytes>>>(
        logits, spec, (float*)d_out, vocab, rows, B, k);
}